// round 16
// baseline (speedup 1.0000x reference)
#include <cuda_runtime.h>
#include <cuda_fp16.h>
#include <math.h>
#include <stdint.h>

#define N_TOK 4096
#define D_DIM 1024
#define H_DIM 2048
#define E_NUM 8
#define NASG  (N_TOK * 2)

#define BM 128
#define BN 128
#define NSTAGE 3
#define TILE_BYTES (BM * 128)                 // 16384 per operand tile
#define STAGE_BYTES (2 * TILE_BYTES)          // A + B = 32KB
#define SMEM_DYN (1024 + 3072 + NSTAGE * STAGE_BYTES)   // ~100KB -> 2 CTAs/SM

#define NT1   4096                            // gemm1 tiles
#define NTC   4096                            // w2 conv chunks
#define NT2   2048                            // gemm2 tiles
#define NTICK (NT1 + NTC + NT2)               // 10240
#define PERSIST_GRID 296                      // 2 per SM x 148 (<= capacity on 152 too)

// ---------------- device scratch ----------------
__device__ int   g_cnt[E_NUM] = {0};          // reset by aux_kernel each pass
__device__ int   g_asg[E_NUM][N_TOK];
__device__ float g_gate[E_NUM][N_TOK];

__device__ int g_ticket = 0;
__device__ int g_conv_done = 0;
__device__ int g_hflag[E_NUM * 32] = {0};

__device__ __align__(256) __half g_xh[(size_t)N_TOK * D_DIM];
__device__ __align__(256) __half g_w1h[(size_t)E_NUM * H_DIM * D_DIM];
__device__ __align__(256) __half g_w2h[(size_t)E_NUM * D_DIM * H_DIM];
__device__ __align__(256) __half g_hh[(size_t)NASG * H_DIM];

// ---------------- helpers ----------------
__device__ __forceinline__ uint32_t smem_u32(const void* p) {
    uint32_t a;
    asm("{ .reg .u64 t; cvta.to.shared.u64 t, %1; cvt.u32.u64 %0, t; }" : "=r"(a) : "l"(p));
    return a;
}
#define SW128(o) ((o) ^ (((o) >> 3) & 0x70))

#define CP16(dst, src) asm volatile("cp.async.cg.shared.global [%0], [%1], 16;" :: "r"(dst), "l"(src))
#define CP_COMMIT()    asm volatile("cp.async.commit_group;" ::: "memory")
#define CP_WAIT1()     asm volatile("cp.async.wait_group 1;" ::: "memory")
#define CP_WAIT0()     asm volatile("cp.async.wait_group 0;" ::: "memory")

#define LDSM4(r0, r1, r2, r3, addr)                                             \
    asm volatile("ldmatrix.sync.aligned.m8n8.x4.shared.b16 {%0,%1,%2,%3}, [%4];" \
        : "=r"(r0), "=r"(r1), "=r"(r2), "=r"(r3) : "r"(addr))

#define MMA16816(d, a0, a1, a2, a3, b0, b1)                                     \
    asm volatile("mma.sync.aligned.m16n8k16.row.col.f32.f16.f16.f32 "           \
        "{%0,%1,%2,%3}, {%4,%5,%6,%7}, {%8,%9}, {%0,%1,%2,%3};"                 \
        : "+f"((d)[0]), "+f"((d)[1]), "+f"((d)[2]), "+f"((d)[3])                \
        : "r"(a0), "r"(a1), "r"(a2), "r"(a3), "r"(b0), "r"(b1))

// 16-elem fp32->fp16 convert helper (4x float4 in, 2x uint4 out)
__device__ __forceinline__ void conv16(const float4* __restrict__ src, uint4* __restrict__ dst, int j) {
    float4 v0 = src[4 * j + 0];
    float4 v1 = src[4 * j + 1];
    float4 v2 = src[4 * j + 2];
    float4 v3 = src[4 * j + 3];
    __half2 a0 = __floats2half2_rn(v0.x, v0.y), a1 = __floats2half2_rn(v0.z, v0.w);
    __half2 a2 = __floats2half2_rn(v1.x, v1.y), a3 = __floats2half2_rn(v1.z, v1.w);
    __half2 a4 = __floats2half2_rn(v2.x, v2.y), a5 = __floats2half2_rn(v2.z, v2.w);
    __half2 a6 = __floats2half2_rn(v3.x, v3.y), a7 = __floats2half2_rn(v3.z, v3.w);
    dst[2 * j + 0] = make_uint4(*(uint32_t*)&a0, *(uint32_t*)&a1,
                                *(uint32_t*)&a2, *(uint32_t*)&a3);
    dst[2 * j + 1] = make_uint4(*(uint32_t*)&a4, *(uint32_t*)&a5,
                                *(uint32_t*)&a6, *(uint32_t*)&a7);
}

// ---------------- fused prologue: w1-convert || out-zero || gating(+x-convert) ----------------
#define NW116 (E_NUM * H_DIM * D_DIM / 16)    // 1048576
#define NW216 (E_NUM * D_DIM * H_DIM / 16)    // 1048576
#define W1BLK (NW116 / 256)                   // 4096
#define ZBLK  (N_TOK * D_DIM / 4 / 256)       // 4096
#define GBLK  (N_TOK / 8)                     // 512
#define PREP_GRID (W1BLK + ZBLK + GBLK)

__global__ void prep_kernel(float4* __restrict__ out4,
                            const float* __restrict__ x,
                            const float* __restrict__ gw,
                            const float4* __restrict__ w1) {
    int b = blockIdx.x;
    if (b < W1BLK) {
        int i = b * blockDim.x + threadIdx.x;
        conv16(w1, (uint4*)g_w1h, i);
    } else if (b < W1BLK + ZBLK) {
        int i = (b - W1BLK) * blockDim.x + threadIdx.x;
        out4[i] = make_float4(0.f, 0.f, 0.f, 0.f);
    } else {
        int bb   = b - W1BLK - ZBLK;
        int tok  = (bb * blockDim.x + threadIdx.x) >> 5;
        int lane = threadIdx.x & 31;
        if (tok >= N_TOK) return;
        const float4* xr = (const float4*)(x + (size_t)tok * D_DIM);
        const float4* gw4 = (const float4*)gw;
        uint2* xh2 = (uint2*)(g_xh + (size_t)tok * D_DIM);
        float acc[E_NUM];
#pragma unroll
        for (int e = 0; e < E_NUM; e++) acc[e] = 0.f;
#pragma unroll
        for (int i = 0; i < D_DIM / 128; i++) {
            float4 xv = xr[lane + i * 32];
            __half2 h0 = __floats2half2_rn(xv.x, xv.y);
            __half2 h1 = __floats2half2_rn(xv.z, xv.w);
            xh2[lane + i * 32] = make_uint2(*(uint32_t*)&h0, *(uint32_t*)&h1);
#pragma unroll
            for (int e = 0; e < E_NUM; e++) {
                float4 wv = __ldg(gw4 + (size_t)e * (D_DIM / 4) + lane + i * 32);
                acc[e] = fmaf(xv.x, wv.x, fmaf(xv.y, wv.y, fmaf(xv.z, wv.z, fmaf(xv.w, wv.w, acc[e]))));
            }
        }
#pragma unroll
        for (int e = 0; e < E_NUM; e++) {
#pragma unroll
            for (int off = 16; off > 0; off >>= 1)
                acc[e] += __shfl_xor_sync(0xffffffffu, acc[e], off);
        }
        if (lane == 0) {
            int i0 = 0; float v0 = acc[0];
#pragma unroll
            for (int e = 1; e < E_NUM; e++)
                if (acc[e] > v0) { v0 = acc[e]; i0 = e; }
            int i1 = -1; float v1 = -3.4e38f;
#pragma unroll
            for (int e = 0; e < E_NUM; e++)
                if (e != i0 && acc[e] > v1) { v1 = acc[e]; i1 = e; }
            float ex = expf(v1 - v0);
            float s  = 1.f + ex;
            int p0 = atomicAdd(&g_cnt[i0], 1);
            g_asg[i0][p0]  = (tok << 1);
            g_gate[i0][p0] = 1.f / s;
            int p1 = atomicAdd(&g_cnt[i1], 1);
            g_asg[i1][p1]  = (tok << 1) | 1;
            g_gate[i1][p1] = ex / s;
        }
    }
}

// aux loss + full state reset for the next graph replay
__global__ void aux_kernel(float* __restrict__ out_aux) {
    float s = 0.f;
#pragma unroll
    for (int e = 0; e < E_NUM; e++) {
        float load = (float)g_cnt[e] / (float)(N_TOK * 2);
        s += load * load;
    }
    *out_aux = 0.01f * (float)E_NUM * s;
#pragma unroll
    for (int e = 0; e < E_NUM; e++) g_cnt[e] = 0;
    g_ticket = 0;
    g_conv_done = 0;
    for (int i = 0; i < E_NUM * 32; i++) g_hflag[i] = 0;
}

// ---------------- HMMA mainloop: 3-stage cp.async + reg double-buffered frags ----------------
#define PREFETCH_CHUNK(cc)                                                         \
    do {                                                                           \
        uint32_t sb = ub + ((cc) % NSTAGE) * STAGE_BYTES;                          \
        size_t ko = (size_t)(cc) * 128;                                            \
        _Pragma("unroll")                                                          \
        for (int t = 0; t < 4; t++) {                                              \
            CP16(sb + dsto[t],              srcA + ko + t * 16);                   \
            CP16(sb + TILE_BYTES + dsto[t], srcB + ko + t * 16);                   \
        }                                                                          \
    } while (0)

#define LDSM_FRAGS(buf, sbase, kk)                                                 \
    do {                                                                           \
        _Pragma("unroll")                                                          \
        for (int mi = 0; mi < 2; mi++)                                             \
            LDSM4(aq[buf][mi][0], aq[buf][mi][1], aq[buf][mi][2], aq[buf][mi][3],  \
                  (sbase) + (aoffs[mi] ^ ((kk) * 32)));                            \
        _Pragma("unroll")                                                          \
        for (int nq = 0; nq < 4; nq++)                                             \
            LDSM4(bq[buf][nq][0], bq[buf][nq][1], bq[buf][nq][2], bq[buf][nq][3],  \
                  (sbase) + (boffs[nq] ^ ((kk) * 32)));                            \
    } while (0)

#define GEMM_MAINLOOP(KDIM, SRC_A, SRC_B)                                          \
    const int C = (KDIM) / 64;                                                     \
    const int rowL  = tid >> 1;                                                    \
    const int cBase = (tid & 1) * 4;                                               \
    const char* srcA = SRC_A;                                                      \
    const char* srcB = SRC_B;                                                      \
    uint32_t dsto[4];                                                              \
    _Pragma("unroll")                                                              \
    for (int t = 0; t < 4; t++)                                                    \
        dsto[t] = SW128((uint32_t)(rowL * 128 + (cBase + t) * 16));                \
    _Pragma("unroll")                                                              \
    for (int c = 0; c < 2; c++) {                                                  \
        PREFETCH_CHUNK(c);                                                         \
        CP_COMMIT();                                                               \
    }                                                                              \
    const int wm = (wid & 3) * 32;                                                 \
    const int wn = (wid >> 2) * 64;                                                \
    uint32_t aoffs[2], boffs[4];                                                   \
    _Pragma("unroll")                                                              \
    for (int mi = 0; mi < 2; mi++)                                                 \
        aoffs[mi] = SW128((uint32_t)((wm + mi * 16 + (lane & 15)) * 128            \
                                     + (lane >> 4) * 16));                         \
    _Pragma("unroll")                                                              \
    for (int nq = 0; nq < 4; nq++)                                                 \
        boffs[nq] = SW128((uint32_t)((wn + nq * 16 + (lane & 15)) * 128            \
                                     + (lane >> 4) * 16)) + TILE_BYTES;            \
    float acc[2][8][4];                                                            \
    _Pragma("unroll")                                                              \
    for (int i = 0; i < 2; i++)                                                    \
        _Pragma("unroll")                                                          \
        for (int j = 0; j < 8; j++)                                                \
            _Pragma("unroll")                                                      \
            for (int q = 0; q < 4; q++) acc[i][j][q] = 0.f;                        \
    uint32_t aq[2][2][4], bq[2][4][4];                                             \
    for (int c = 0; c < C; c++) {                                                  \
        if (c >= C - 2) { CP_WAIT0(); } else { CP_WAIT1(); }                       \
        __syncthreads();                                                           \
        uint32_t sbase = ub + (c % NSTAGE) * STAGE_BYTES;                          \
        LDSM_FRAGS(0, sbase, 0);                                                   \
        int cn = c + 2;                                                            \
        if (cn < C) {                                                              \
            PREFETCH_CHUNK(cn);                                                    \
            CP_COMMIT();                                                           \
        }                                                                          \
        _Pragma("unroll")                                                          \
        for (int kk = 0; kk < 4; kk++) {                                           \
            int cur = kk & 1;                                                      \
            if (kk < 3) LDSM_FRAGS(cur ^ 1, sbase, kk + 1);                        \
            _Pragma("unroll")                                                      \
            for (int mi = 0; mi < 2; mi++)                                         \
                _Pragma("unroll")                                                  \
                for (int nq = 0; nq < 4; nq++) {                                   \
                    MMA16816(acc[mi][nq * 2],     aq[cur][mi][0], aq[cur][mi][1],  \
                             aq[cur][mi][2], aq[cur][mi][3],                       \
                             bq[cur][nq][0], bq[cur][nq][2]);                      \
                    MMA16816(acc[mi][nq * 2 + 1], aq[cur][mi][0], aq[cur][mi][1],  \
                             aq[cur][mi][2], aq[cur][mi][3],                       \
                             bq[cur][nq][1], bq[cur][nq][3]);                      \
                }                                                                  \
        }                                                                          \
    }

// ---------------- tile bodies ----------------
__device__ void gemm1_tile(int bb, const float* __restrict__ b1, char* base) {
    const int e    = bb >> 9;
    const int mblk = bb & 31;
    const int cnt  = g_cnt[e];
    const int m0   = mblk * BM;
    if (m0 >= cnt) return;
    const int n0   = ((bb >> 5) & 15) * BN;

    int* sAsg = (int*)base;
    uint32_t ub = smem_u32(base) + 3072;

    const int tid = threadIdx.x, wid = tid >> 5, lane = tid & 31;
    if (tid < BM) {
        int r = m0 + tid;
        sAsg[tid] = (r < cnt) ? g_asg[e][r] : -1;
    }
    __syncthreads();

    int aidL = sAsg[tid >> 1];
    int tokL = (aidL >= 0) ? (aidL >> 1) : 0;
    size_t aoff = ((size_t)tokL * D_DIM + (size_t)(tid & 1) * 32) * 2;
    size_t boff = (((size_t)e * H_DIM + n0 + (tid >> 1)) * D_DIM + (size_t)(tid & 1) * 32) * 2;

    GEMM_MAINLOOP(D_DIM,
        (const char*)g_xh + aoff,
        (const char*)g_w1h + boff)

    const float* b1e = b1 + (size_t)e * H_DIM + n0;
    float bias[8][2];
#pragma unroll
    for (int ni = 0; ni < 8; ni++) {
        int cb = wn + ni * 8 + (lane & 3) * 2;
        bias[ni][0] = __ldg(b1e + cb);
        bias[ni][1] = __ldg(b1e + cb + 1);
    }
#pragma unroll
    for (int mi = 0; mi < 2; mi++) {
#pragma unroll
        for (int h = 0; h < 2; h++) {
            int row = wm + mi * 16 + (lane >> 2) + h * 8;
            int aid = sAsg[row];
            if (aid < 0) continue;
            __half* hh = g_hh + (size_t)aid * H_DIM + n0;
#pragma unroll
            for (int ni = 0; ni < 8; ni++) {
                int cb = wn + ni * 8 + (lane & 3) * 2;
                float v0 = acc[mi][ni][h * 2]     + bias[ni][0];
                float v1 = acc[mi][ni][h * 2 + 1] + bias[ni][1];
                v0 = v0 / (1.f + __expf(-v0));
                v1 = v1 / (1.f + __expf(-v1));
                __half2 p = __floats2half2_rn(v0, v1);
                *(uint32_t*)(hh + cb) = *(uint32_t*)&p;
            }
        }
    }
    // publish: all h stores visible, then bump the (e, mblk) flag
    __threadfence();
    __syncthreads();
    if (tid == 0) atomicAdd(&g_hflag[e * 32 + mblk], 1);
}

__device__ void gemm2_tile(int t2, const float* __restrict__ b2,
                           float* __restrict__ out, char* base) {
    const int e    = t2 >> 8;
    const int mblk = t2 & 31;
    const int cnt  = g_cnt[e];
    const int m0   = mblk * BM;
    if (m0 >= cnt) return;
    const int n0   = ((t2 >> 5) & 7) * BN;

    const int tid = threadIdx.x, wid = tid >> 5, lane = tid & 31;

    // wait for w2 conversion + all 16 gemm1 n-tiles of this (e, mblk)
    if (tid == 0) {
        while (atomicAdd(&g_conv_done, 0) < NTC) __nanosleep(128);
        while (atomicAdd(&g_hflag[e * 32 + mblk], 0) < 16) __nanosleep(128);
    }
    __syncthreads();
    __threadfence();

    int*   sAsg  = (int*)base;
    float* sGate = (float*)(base + 512);
    uint32_t ub = smem_u32(base) + 3072;

    if (tid < BM) {
        int r = m0 + tid;
        sAsg[tid]  = (r < cnt) ? g_asg[e][r] : -1;
        sGate[tid] = (r < cnt) ? g_gate[e][r] : 0.f;
    }
    __syncthreads();

    int aidL = sAsg[tid >> 1];
    int arwL = (aidL >= 0) ? aidL : 0;
    size_t aoff = ((size_t)arwL * H_DIM + (size_t)(tid & 1) * 32) * 2;
    size_t boff = (((size_t)e * D_DIM + n0 + (tid >> 1)) * H_DIM + (size_t)(tid & 1) * 32) * 2;

    GEMM_MAINLOOP(H_DIM,
        (const char*)g_hh + aoff,
        (const char*)g_w2h + boff)

    const float* b2e = b2 + (size_t)e * D_DIM + n0;
    float bias[8][2];
#pragma unroll
    for (int ni = 0; ni < 8; ni++) {
        int cb = wn + ni * 8 + (lane & 3) * 2;
        bias[ni][0] = __ldg(b2e + cb);
        bias[ni][1] = __ldg(b2e + cb + 1);
    }
#pragma unroll
    for (int mi = 0; mi < 2; mi++) {
#pragma unroll
        for (int h = 0; h < 2; h++) {
            int row = wm + mi * 16 + (lane >> 2) + h * 8;
            int aid = sAsg[row];
            if (aid < 0) continue;
            float gte = sGate[row];
            float* orow = out + (size_t)(aid >> 1) * D_DIM + n0;
#pragma unroll
            for (int ni = 0; ni < 8; ni++) {
                int cb = wn + ni * 8 + (lane & 3) * 2;
                atomicAdd(orow + cb,     gte * (acc[mi][ni][h * 2]     + bias[ni][0]));
                atomicAdd(orow + cb + 1, gte * (acc[mi][ni][h * 2 + 1] + bias[ni][1]));
            }
        }
    }
}

// ---------------- persistent fused kernel: gemm1 || w2-convert -> gemm2 ----------------
__global__ __launch_bounds__(256, 2) void moe_fused(const float* __restrict__ b1,
                                                    const float* __restrict__ b2,
                                                    const float4* __restrict__ w2src,
                                                    float* __restrict__ out) {
    extern __shared__ char dsm[];
    char* base = (char*)(((uintptr_t)dsm + 1023) & ~(uintptr_t)1023);
    __shared__ int s_t;

    for (;;) {
        __syncthreads();                       // protect smem + s_t reuse across tiles
        if (threadIdx.x == 0) s_t = atomicAdd(&g_ticket, 1);
        __syncthreads();
        int t = s_t;
        if (t >= NTICK) return;

        if (t < NT1 + NTC) {
            if (t & 1) {
                // w2 conversion chunk (hidden under gemm1 issue-bound work)
                int i = (t >> 1) * 256 + threadIdx.x;   // < NW216
                conv16(w2src, (uint4*)g_w2h, i);
                __threadfence();
                __syncthreads();
                if (threadIdx.x == 0) atomicAdd(&g_conv_done, 1);
            } else {
                gemm1_tile(t >> 1, b1, base);
            }
        } else {
            gemm2_tile(t - (NT1 + NTC), b2, out, base);
        }
    }
}

// ---------------- launch ----------------
extern "C" void kernel_launch(void* const* d_in, const int* in_sizes, int n_in,
                              void* d_out, int out_size) {
    const float* x  = (const float*)d_in[0];
    const float* gw = (const float*)d_in[1];
    const float* w1 = (const float*)d_in[2];
    const float* b1 = (const float*)d_in[3];
    const float* w2 = (const float*)d_in[4];
    const float* b2 = (const float*)d_in[5];
    float* out = (float*)d_out;

    cudaFuncSetAttribute(moe_fused, cudaFuncAttributeMaxDynamicSharedMemorySize, SMEM_DYN);

    // 1: fused prologue (w1-convert || out-zero || gating+x-convert)
    prep_kernel<<<PREP_GRID, 256>>>((float4*)out, x, gw, (const float4*)w1);
    // 2: persistent fused gemm1 + w2-convert + gemm2
    moe_fused<<<PERSIST_GRID, 256, SMEM_DYN>>>(b1, b2, (const float4*)w2, out);
    // 3: aux loss + state reset for next replay
    aux_kernel<<<1, 1>>>(out + (out_size - 1));
}

// round 17
// speedup vs baseline: 1.1603x; 1.1603x over previous
#include <cuda_runtime.h>
#include <cuda_fp16.h>
#include <math.h>
#include <stdint.h>

#define N_TOK 4096
#define D_DIM 1024
#define H_DIM 2048
#define E_NUM 8
#define NASG  (N_TOK * 2)

#define BM 128
#define BN 128
#define NSTAGE 3
#define TILE_BYTES (BM * 128)                 // 16384 per operand tile
#define STAGE_BYTES (2 * TILE_BYTES)          // A + B = 32KB
#define SMEM_DYN (1024 + 3072 + NSTAGE * STAGE_BYTES)   // ~100KB -> 2 CTAs/SM

// ---------------- device scratch ----------------
__device__ int   g_cnt[E_NUM] = {0};          // reset by aux_kernel each pass
__device__ int   g_asg[E_NUM][N_TOK];
__device__ float g_gate[E_NUM][N_TOK];

__device__ __align__(256) __half g_xh[(size_t)N_TOK * D_DIM];
__device__ __align__(256) __half g_w1h[(size_t)E_NUM * H_DIM * D_DIM];
__device__ __align__(256) __half g_w2h[(size_t)E_NUM * D_DIM * H_DIM];
__device__ __align__(256) __half g_hh[(size_t)NASG * H_DIM];

// ---------------- helpers ----------------
__device__ __forceinline__ uint32_t smem_u32(const void* p) {
    uint32_t a;
    asm("{ .reg .u64 t; cvta.to.shared.u64 t, %1; cvt.u32.u64 %0, t; }" : "=r"(a) : "l"(p));
    return a;
}
#define SW128(o) ((o) ^ (((o) >> 3) & 0x70))

#define CP16(dst, src) asm volatile("cp.async.cg.shared.global [%0], [%1], 16;" :: "r"(dst), "l"(src))
#define CP_COMMIT()    asm volatile("cp.async.commit_group;" ::: "memory")
#define CP_WAIT1()     asm volatile("cp.async.wait_group 1;" ::: "memory")
#define CP_WAIT0()     asm volatile("cp.async.wait_group 0;" ::: "memory")

#define LDSM4(r0, r1, r2, r3, addr)                                             \
    asm volatile("ldmatrix.sync.aligned.m8n8.x4.shared.b16 {%0,%1,%2,%3}, [%4];" \
        : "=r"(r0), "=r"(r1), "=r"(r2), "=r"(r3) : "r"(addr))

#define MMA16816(d, a0, a1, a2, a3, b0, b1)                                     \
    asm volatile("mma.sync.aligned.m16n8k16.row.col.f32.f16.f16.f32 "           \
        "{%0,%1,%2,%3}, {%4,%5,%6,%7}, {%8,%9}, {%0,%1,%2,%3};"                 \
        : "+f"((d)[0]), "+f"((d)[1]), "+f"((d)[2]), "+f"((d)[3])                \
        : "r"(a0), "r"(a1), "r"(a2), "r"(a3), "r"(b0), "r"(b1))

// vectorized f32x2 global reduction (sm_90+)
#define REDG2(addr, v0, v1)                                                      \
    asm volatile("red.global.add.v2.f32 [%0], {%1, %2};"                         \
        :: "l"(addr), "f"(v0), "f"(v1) : "memory")

// 16-elem fp32->fp16 convert helper (4x float4 in, 2x uint4 out)
__device__ __forceinline__ void conv16(const float4* __restrict__ src, uint4* __restrict__ dst, int j) {
    float4 v0 = src[4 * j + 0];
    float4 v1 = src[4 * j + 1];
    float4 v2 = src[4 * j + 2];
    float4 v3 = src[4 * j + 3];
    __half2 a0 = __floats2half2_rn(v0.x, v0.y), a1 = __floats2half2_rn(v0.z, v0.w);
    __half2 a2 = __floats2half2_rn(v1.x, v1.y), a3 = __floats2half2_rn(v1.z, v1.w);
    __half2 a4 = __floats2half2_rn(v2.x, v2.y), a5 = __floats2half2_rn(v2.z, v2.w);
    __half2 a6 = __floats2half2_rn(v3.x, v3.y), a7 = __floats2half2_rn(v3.z, v3.w);
    dst[2 * j + 0] = make_uint4(*(uint32_t*)&a0, *(uint32_t*)&a1,
                                *(uint32_t*)&a2, *(uint32_t*)&a3);
    dst[2 * j + 1] = make_uint4(*(uint32_t*)&a4, *(uint32_t*)&a5,
                                *(uint32_t*)&a6, *(uint32_t*)&a7);
}

// ---------------- fused prologue: w1-convert || out-zero || gating(+x-convert) ----------------
#define NW116 (E_NUM * H_DIM * D_DIM / 16)    // 1048576
#define NW216 (E_NUM * D_DIM * H_DIM / 16)    // 1048576
#define W1BLK (NW116 / 256)                   // 4096
#define ZBLK  (N_TOK * D_DIM / 4 / 256)       // 4096
#define GBLK  (N_TOK / 8)                     // 512
#define PREP_GRID (W1BLK + ZBLK + GBLK)

__global__ void prep_kernel(float4* __restrict__ out4,
                            const float* __restrict__ x,
                            const float* __restrict__ gw,
                            const float4* __restrict__ w1) {
    int b = blockIdx.x;
    if (b < W1BLK) {
        int i = b * blockDim.x + threadIdx.x;
        conv16(w1, (uint4*)g_w1h, i);
    } else if (b < W1BLK + ZBLK) {
        int i = (b - W1BLK) * blockDim.x + threadIdx.x;
        out4[i] = make_float4(0.f, 0.f, 0.f, 0.f);
    } else {
        int bb   = b - W1BLK - ZBLK;
        int tok  = (bb * blockDim.x + threadIdx.x) >> 5;
        int lane = threadIdx.x & 31;
        if (tok >= N_TOK) return;
        const float4* xr = (const float4*)(x + (size_t)tok * D_DIM);
        const float4* gw4 = (const float4*)gw;
        uint2* xh2 = (uint2*)(g_xh + (size_t)tok * D_DIM);
        float acc[E_NUM];
#pragma unroll
        for (int e = 0; e < E_NUM; e++) acc[e] = 0.f;
#pragma unroll
        for (int i = 0; i < D_DIM / 128; i++) {
            float4 xv = xr[lane + i * 32];
            __half2 h0 = __floats2half2_rn(xv.x, xv.y);
            __half2 h1 = __floats2half2_rn(xv.z, xv.w);
            xh2[lane + i * 32] = make_uint2(*(uint32_t*)&h0, *(uint32_t*)&h1);
#pragma unroll
            for (int e = 0; e < E_NUM; e++) {
                float4 wv = __ldg(gw4 + (size_t)e * (D_DIM / 4) + lane + i * 32);
                acc[e] = fmaf(xv.x, wv.x, fmaf(xv.y, wv.y, fmaf(xv.z, wv.z, fmaf(xv.w, wv.w, acc[e]))));
            }
        }
#pragma unroll
        for (int e = 0; e < E_NUM; e++) {
#pragma unroll
            for (int off = 16; off > 0; off >>= 1)
                acc[e] += __shfl_xor_sync(0xffffffffu, acc[e], off);
        }
        if (lane == 0) {
            int i0 = 0; float v0 = acc[0];
#pragma unroll
            for (int e = 1; e < E_NUM; e++)
                if (acc[e] > v0) { v0 = acc[e]; i0 = e; }
            int i1 = -1; float v1 = -3.4e38f;
#pragma unroll
            for (int e = 0; e < E_NUM; e++)
                if (e != i0 && acc[e] > v1) { v1 = acc[e]; i1 = e; }
            float ex = expf(v1 - v0);
            float s  = 1.f + ex;
            int p0 = atomicAdd(&g_cnt[i0], 1);
            g_asg[i0][p0]  = (tok << 1);
            g_gate[i0][p0] = 1.f / s;
            int p1 = atomicAdd(&g_cnt[i1], 1);
            g_asg[i1][p1]  = (tok << 1) | 1;
            g_gate[i1][p1] = ex / s;
        }
    }
}

// aux loss + counter reset (trailing launch; leaves g_cnt = 0 for the next replay)
__global__ void aux_kernel(float* __restrict__ out_aux) {
    float s = 0.f;
#pragma unroll
    for (int e = 0; e < E_NUM; e++) {
        float load = (float)g_cnt[e] / (float)(N_TOK * 2);
        s += load * load;
    }
    *out_aux = 0.01f * (float)E_NUM * s;
#pragma unroll
    for (int e = 0; e < E_NUM; e++) g_cnt[e] = 0;
}

// ---------------- HMMA mainloop: 3-stage cp.async (2 CTAs/SM) + reg double-buffered frags ----------------
#define PREFETCH_CHUNK(cc)                                                         \
    do {                                                                           \
        uint32_t sb = ub + ((cc) % NSTAGE) * STAGE_BYTES;                          \
        size_t ko = (size_t)(cc) * 128;                                            \
        _Pragma("unroll")                                                          \
        for (int t = 0; t < 4; t++) {                                              \
            CP16(sb + dsto[t],              srcA + ko + t * 16);                   \
            CP16(sb + TILE_BYTES + dsto[t], srcB + ko + t * 16);                   \
        }                                                                          \
    } while (0)

#define LDSM_FRAGS(buf, sbase, kk)                                                 \
    do {                                                                           \
        _Pragma("unroll")                                                          \
        for (int mi = 0; mi < 2; mi++)                                             \
            LDSM4(aq[buf][mi][0], aq[buf][mi][1], aq[buf][mi][2], aq[buf][mi][3],  \
                  (sbase) + (aoffs[mi] ^ ((kk) * 32)));                            \
        _Pragma("unroll")                                                          \
        for (int nq = 0; nq < 4; nq++)                                             \
            LDSM4(bq[buf][nq][0], bq[buf][nq][1], bq[buf][nq][2], bq[buf][nq][3],  \
                  (sbase) + (boffs[nq] ^ ((kk) * 32)));                            \
    } while (0)

#define GEMM_MAINLOOP(KDIM, SRC_A, SRC_B)                                          \
    const int C = (KDIM) / 64;                                                     \
    const int rowL  = tid >> 1;                                                    \
    const int cBase = (tid & 1) * 4;                                               \
    const char* srcA = SRC_A;                                                      \
    const char* srcB = SRC_B;                                                      \
    uint32_t dsto[4];                                                              \
    _Pragma("unroll")                                                              \
    for (int t = 0; t < 4; t++)                                                    \
        dsto[t] = SW128((uint32_t)(rowL * 128 + (cBase + t) * 16));                \
    _Pragma("unroll")                                                              \
    for (int c = 0; c < 2; c++) {                                                  \
        PREFETCH_CHUNK(c);                                                         \
        CP_COMMIT();                                                               \
    }                                                                              \
    const int wm = (wid & 3) * 32;                                                 \
    const int wn = (wid >> 2) * 64;                                                \
    uint32_t aoffs[2], boffs[4];                                                   \
    _Pragma("unroll")                                                              \
    for (int mi = 0; mi < 2; mi++)                                                 \
        aoffs[mi] = SW128((uint32_t)((wm + mi * 16 + (lane & 15)) * 128            \
                                     + (lane >> 4) * 16));                         \
    _Pragma("unroll")                                                              \
    for (int nq = 0; nq < 4; nq++)                                                 \
        boffs[nq] = SW128((uint32_t)((wn + nq * 16 + (lane & 15)) * 128            \
                                     + (lane >> 4) * 16)) + TILE_BYTES;            \
    float acc[2][8][4];                                                            \
    _Pragma("unroll")                                                              \
    for (int i = 0; i < 2; i++)                                                    \
        _Pragma("unroll")                                                          \
        for (int j = 0; j < 8; j++)                                                \
            _Pragma("unroll")                                                      \
            for (int q = 0; q < 4; q++) acc[i][j][q] = 0.f;                        \
    uint32_t aq[2][2][4], bq[2][4][4];                                             \
    for (int c = 0; c < C; c++) {                                                  \
        if (c >= C - 2) { CP_WAIT0(); } else { CP_WAIT1(); }                       \
        __syncthreads();                                                           \
        uint32_t sbase = ub + (c % NSTAGE) * STAGE_BYTES;                          \
        LDSM_FRAGS(0, sbase, 0);                                                   \
        int cn = c + 2;                                                            \
        if (cn < C) {                                                              \
            PREFETCH_CHUNK(cn);                                                    \
            CP_COMMIT();                                                           \
        }                                                                          \
        _Pragma("unroll")                                                          \
        for (int kk = 0; kk < 4; kk++) {                                           \
            int cur = kk & 1;                                                      \
            if (kk < 3) LDSM_FRAGS(cur ^ 1, sbase, kk + 1);                        \
            _Pragma("unroll")                                                      \
            for (int mi = 0; mi < 2; mi++)                                         \
                _Pragma("unroll")                                                  \
                for (int nq = 0; nq < 4; nq++) {                                   \
                    MMA16816(acc[mi][nq * 2],     aq[cur][mi][0], aq[cur][mi][1],  \
                             aq[cur][mi][2], aq[cur][mi][3],                       \
                             bq[cur][nq][0], bq[cur][nq][2]);                      \
                    MMA16816(acc[mi][nq * 2 + 1], aq[cur][mi][0], aq[cur][mi][1],  \
                             aq[cur][mi][2], aq[cur][mi][3],                       \
                             bq[cur][nq][1], bq[cur][nq][3]);                      \
                }                                                                  \
        }                                                                          \
    }

// GEMM1 (1-D grid, alternating with w2-converter blocks):
//   odd blocks: convert one w2 chunk and exit (hidden under GEMM issue-bound work)
//   even blocks: h[aid] = silu(x[tok] @ w1[e]^T + b1[e]) -> fp16
__global__ __launch_bounds__(256, 2) void gemm1_mma(const float* __restrict__ b1,
                                                    const float4* __restrict__ w2src) {
    const int b = blockIdx.x;
    if (b & 1) {
        int i = (b >> 1) * 256 + threadIdx.x;   // < NW216
        conv16(w2src, (uint4*)g_w2h, i);
        return;
    }
    const int bb = b >> 1;                      // 0..4095
    const int e  = bb >> 9;
    const int cnt = g_cnt[e];
    const int m0 = (bb & 31) * BM;              // m fastest for L2 weight reuse
    if (m0 >= cnt) return;
    const int n0 = ((bb >> 5) & 15) * BN;

    extern __shared__ char dsm[];
    char* base = (char*)(((uintptr_t)dsm + 1023) & ~(uintptr_t)1023);
    int* sAsg = (int*)base;
    uint32_t ub = smem_u32(base) + 3072;

    const int tid = threadIdx.x, wid = tid >> 5, lane = tid & 31;
    if (tid < BM) {
        int r = m0 + tid;
        sAsg[tid] = (r < cnt) ? g_asg[e][r] : -1;
    }
    __syncthreads();

    int aidL = sAsg[tid >> 1];
    int tokL = (aidL >= 0) ? (aidL >> 1) : 0;
    size_t aoff = ((size_t)tokL * D_DIM + (size_t)(tid & 1) * 32) * 2;
    size_t boff = (((size_t)e * H_DIM + n0 + (tid >> 1)) * D_DIM + (size_t)(tid & 1) * 32) * 2;

    GEMM_MAINLOOP(D_DIM,
        (const char*)g_xh + aoff,
        (const char*)g_w1h + boff)

    const float* b1e = b1 + (size_t)e * H_DIM + n0;
    float bias[8][2];
#pragma unroll
    for (int ni = 0; ni < 8; ni++) {
        int cb = wn + ni * 8 + (lane & 3) * 2;
        bias[ni][0] = __ldg(b1e + cb);
        bias[ni][1] = __ldg(b1e + cb + 1);
    }
#pragma unroll
    for (int mi = 0; mi < 2; mi++) {
#pragma unroll
        for (int h = 0; h < 2; h++) {
            int row = wm + mi * 16 + (lane >> 2) + h * 8;
            int aid = sAsg[row];
            if (aid < 0) continue;
            __half* hh = g_hh + (size_t)aid * H_DIM + n0;
#pragma unroll
            for (int ni = 0; ni < 8; ni++) {
                int cb = wn + ni * 8 + (lane & 3) * 2;
                float v0 = acc[mi][ni][h * 2]     + bias[ni][0];
                float v1 = acc[mi][ni][h * 2 + 1] + bias[ni][1];
                v0 = v0 / (1.f + __expf(-v0));
                v1 = v1 / (1.f + __expf(-v1));
                __half2 p = __floats2half2_rn(v0, v1);
                *(uint32_t*)(hh + cb) = *(uint32_t*)&p;
            }
        }
    }
}

// GEMM2: out[tok] += gate * ( h[aid] @ w2[e]^T + b2[e] )  -- vectorized red.v2
__global__ __launch_bounds__(256, 2) void gemm2_mma(const float* __restrict__ b2,
                                                    float* __restrict__ out) {
    const int e   = blockIdx.z;
    const int cnt = g_cnt[e];
    const int m0  = blockIdx.x * BM;
    if (m0 >= cnt) return;
    const int n0  = blockIdx.y * BN;

    extern __shared__ char dsm[];
    char* base = (char*)(((uintptr_t)dsm + 1023) & ~(uintptr_t)1023);
    int*   sAsg  = (int*)base;
    float* sGate = (float*)(base + 512);
    uint32_t ub = smem_u32(base) + 3072;

    const int tid = threadIdx.x, wid = tid >> 5, lane = tid & 31;
    if (tid < BM) {
        int r = m0 + tid;
        sAsg[tid]  = (r < cnt) ? g_asg[e][r] : -1;
        sGate[tid] = (r < cnt) ? g_gate[e][r] : 0.f;
    }
    __syncthreads();

    int aidL = sAsg[tid >> 1];
    int arwL = (aidL >= 0) ? aidL : 0;
    size_t aoff = ((size_t)arwL * H_DIM + (size_t)(tid & 1) * 32) * 2;
    size_t boff = (((size_t)e * D_DIM + n0 + (tid >> 1)) * H_DIM + (size_t)(tid & 1) * 32) * 2;

    GEMM_MAINLOOP(H_DIM,
        (const char*)g_hh + aoff,
        (const char*)g_w2h + boff)

    const float* b2e = b2 + (size_t)e * D_DIM + n0;
    float bias[8][2];
#pragma unroll
    for (int ni = 0; ni < 8; ni++) {
        int cb = wn + ni * 8 + (lane & 3) * 2;
        bias[ni][0] = __ldg(b2e + cb);
        bias[ni][1] = __ldg(b2e + cb + 1);
    }
#pragma unroll
    for (int mi = 0; mi < 2; mi++) {
#pragma unroll
        for (int h = 0; h < 2; h++) {
            int row = wm + mi * 16 + (lane >> 2) + h * 8;
            int aid = sAsg[row];
            if (aid < 0) continue;
            float gte = sGate[row];
            float* orow = out + (size_t)(aid >> 1) * D_DIM + n0;
#pragma unroll
            for (int ni = 0; ni < 8; ni++) {
                int cb = wn + ni * 8 + (lane & 3) * 2;
                float v0 = gte * (acc[mi][ni][h * 2]     + bias[ni][0]);
                float v1 = gte * (acc[mi][ni][h * 2 + 1] + bias[ni][1]);
                REDG2(orow + cb, v0, v1);
            }
        }
    }
}

// ---------------- launch ----------------
extern "C" void kernel_launch(void* const* d_in, const int* in_sizes, int n_in,
                              void* d_out, int out_size) {
    const float* x  = (const float*)d_in[0];
    const float* gw = (const float*)d_in[1];
    const float* w1 = (const float*)d_in[2];
    const float* b1 = (const float*)d_in[3];
    const float* w2 = (const float*)d_in[4];
    const float* b2 = (const float*)d_in[5];
    float* out = (float*)d_out;

    cudaFuncSetAttribute(gemm1_mma, cudaFuncAttributeMaxDynamicSharedMemorySize, SMEM_DYN);
    cudaFuncSetAttribute(gemm2_mma, cudaFuncAttributeMaxDynamicSharedMemorySize, SMEM_DYN);

    // 1: fused prologue (w1-convert || out-zero || gating+x-convert)
    prep_kernel<<<PREP_GRID, 256>>>((float4*)out, x, gw, (const float4*)w1);
    // 2: gemm1 (even blocks) interleaved with w2 conversion (odd blocks)
    gemm1_mma<<<2 * 4096, 256, SMEM_DYN>>>(b1, (const float4*)w2);
    // 3: gemm2
    dim3 g2(N_TOK / BM, D_DIM / BN, E_NUM);   // (32, 8, 8)
    gemm2_mma<<<g2, 256, SMEM_DYN>>>(b2, out);
    // 4: aux loss + counter reset for next replay
    aux_kernel<<<1, 1>>>(out + (out_size - 1));
}